// round 1
// baseline (speedup 1.0000x reference)
#include <cuda_runtime.h>

// ---------------------------------------------------------------------------
// MessageProp fused kernel, fp32 baseline.
//
// Math folding (done in two tiny precompute kernels):
//   csum[b,d]  = sum_k components[k,b,d]
//   right[b,f] = csum @ (Wu@Wm)^T + (K*Wu@bm + bu)        (Wc, bc)
//   h0         = relu([sig | csum] @ Wcat^T + b0c)
//     where Wcat[o, 0:128]   = W0[o, 0:128]
//           Wcat[o, 128:256] = sum_f W0[o,128+f] * Wc[f,:]
//           b0c[o]           = sum_f W0[o,128+f] * bc[f] + b0[o]
//   h1 = relu(h0@W1^T+b1); h2 = relu(h1@W2^T+b2); out = h2@W3^T+b3
// ---------------------------------------------------------------------------

#define D_   128
#define H_   132
#define TPB  256
#define ROWS 64      // rows per CTA
#define RT   8       // rows per thread (ty = warp id 0..7)
// lane tx = 0..31; outputs o = tx + 32*j, j < OTN

__device__ float g_Wcat[H_ * 2 * D_];   // [132][256] folded layer-0 weight
__device__ float g_b0c[H_];
__device__ float g_Wc[D_ * D_];
__device__ float g_bc[D_];

// ---- precompute A: Wc[f][d] = sum_e Wu[f][e]*Wm[e][d]; bc = K*(Wu@bm) + bu
__global__ void precompA(const float* __restrict__ Wm, const float* __restrict__ bm,
                         const float* __restrict__ Wu, const float* __restrict__ bu,
                         int K)
{
    __shared__ float sWu[D_];
    int f = blockIdx.x, d = threadIdx.x;
    sWu[d] = Wu[f * D_ + d];
    __syncthreads();
    float acc = 0.f;
#pragma unroll 8
    for (int e = 0; e < D_; e++) acc += sWu[e] * Wm[e * D_ + d];
    g_Wc[f * D_ + d] = acc;
    if (d == 0) {
        float s = 0.f;
        for (int e = 0; e < D_; e++) s += sWu[e] * bm[e];
        g_bc[f] = (float)K * s + bu[f];
    }
}

// ---- precompute B: build Wcat and b0c (depends on g_Wc/g_bc; separate launch)
__global__ void precompB(const float* __restrict__ W0, const float* __restrict__ b0)
{
    __shared__ float sW0r[D_];
    int o = blockIdx.x, d = threadIdx.x;
    sW0r[d] = W0[o * 2 * D_ + D_ + d];
    g_Wcat[o * 2 * D_ + d] = W0[o * 2 * D_ + d];
    __syncthreads();
    float acc = 0.f;
#pragma unroll 8
    for (int f = 0; f < D_; f++) acc += sW0r[f] * g_Wc[f * D_ + d];
    g_Wcat[o * 2 * D_ + D_ + d] = acc;
    if (d == 0) {
        float s = 0.f;
        for (int f = 0; f < D_; f++) s += sW0r[f] * g_bc[f];
        g_b0c[o] = s + b0[o];
    }
}

// ---- SMEM layout (floats)
constexpr int SX_STRIDE = 256;          // layer-0 input [64][256]
constexpr int SH_STRIDE = 132;          // activations  [64][132]
constexpr int SW_STRIDE = 132;          // staged weight tile [132][<=132]  (132 % 32 == 4 -> good banks)
constexpr int SH_OFF = ROWS * SX_STRIDE;            // 16384
constexpr int SW_OFF = SH_OFF + ROWS * SH_STRIDE;   // 24832
constexpr int SMEM_FLOATS = SW_OFF + H_ * SW_STRIDE; // 42256
constexpr int SMEM_BYTES = SMEM_FLOATS * 4;          // 169024

template<int IN, int OUT, int OTN, int CH, bool RELU>
__device__ __forceinline__ void layer(const float* X, int xs,
                                      float* Y, int ys,
                                      const float* __restrict__ W,
                                      const float* __restrict__ bias,
                                      float* Sw, int tid)
{
    const int tx = tid & 31;
    const int ty = tid >> 5;

    float acc[RT][OTN];
#pragma unroll
    for (int j = 0; j < OTN; j++) {
        int o = tx + 32 * j;
        float bv = (o < OUT) ? bias[o] : 0.f;
#pragma unroll
        for (int a = 0; a < RT; a++) acc[a][j] = bv;
    }

    for (int i0 = 0; i0 < IN; i0 += CH) {
        __syncthreads();   // prev consumers of Sw / prev layer stores done
        // stage W[0:OUT][i0:i0+CH] into Sw (coalesced LDG from L2, float4)
        const int n4 = OUT * (CH / 4);
        for (int idx = tid; idx < n4; idx += TPB) {
            int o = idx / (CH / 4);
            int c = (idx % (CH / 4)) * 4;
            *(float4*)&Sw[o * SW_STRIDE + c] = *(const float4*)&W[o * IN + i0 + c];
        }
        __syncthreads();

        for (int c = 0; c < CH; c += 4) {
            float4 xv[RT];
#pragma unroll
            for (int a = 0; a < RT; a++)
                xv[a] = *(const float4*)&X[(ty * RT + a) * xs + i0 + c];
            float4 wv[OTN];
#pragma unroll
            for (int j = 0; j < OTN; j++) {
                int o = tx + 32 * j;
                wv[j] = (o < OUT) ? *(const float4*)&Sw[o * SW_STRIDE + c]
                                  : make_float4(0.f, 0.f, 0.f, 0.f);
            }
#pragma unroll
            for (int a = 0; a < RT; a++)
#pragma unroll
                for (int j = 0; j < OTN; j++) {
                    acc[a][j] += xv[a].x * wv[j].x;
                    acc[a][j] += xv[a].y * wv[j].y;
                    acc[a][j] += xv[a].z * wv[j].z;
                    acc[a][j] += xv[a].w * wv[j].w;
                }
        }
    }

#pragma unroll
    for (int j = 0; j < OTN; j++) {
        int o = tx + 32 * j;
        if (o < OUT) {
#pragma unroll
            for (int a = 0; a < RT; a++) {
                float v = acc[a][j];
                if (RELU) v = fmaxf(v, 0.f);
                Y[(ty * RT + a) * ys + o] = v;
            }
        }
    }
}

__global__ __launch_bounds__(TPB, 1)
void fused_kernel(const float* __restrict__ sig,
                  const float* __restrict__ comps,
                  const float* __restrict__ W1, const float* __restrict__ b1,
                  const float* __restrict__ W2, const float* __restrict__ b2,
                  const float* __restrict__ W3, const float* __restrict__ b3,
                  float* __restrict__ out, int B, int K)
{
    extern __shared__ float sm[];
    float* Sx = sm;
    float* Sh = sm + SH_OFF;
    float* Sw = sm + SW_OFF;
    const int tid = threadIdx.x;
    const long row0 = (long)blockIdx.x * ROWS;

    // ---- load signal tile + on-the-fly component sum (csum) into Sx[64][256]
    const float4* sig4 = (const float4*)sig;
    const float4* cmp4 = (const float4*)comps;
    const long strideK = (long)B * (D_ / 4);
    for (int idx = tid; idx < ROWS * (D_ / 4); idx += TPB) {
        int r  = idx >> 5;       // D_/4 = 32
        int c4 = idx & 31;
        long base = (row0 + r) * 32 + c4;
        float4 v = sig4[base];
        *(float4*)&Sx[r * SX_STRIDE + c4 * 4] = v;
        float4 s = make_float4(0.f, 0.f, 0.f, 0.f);
        for (int k = 0; k < K; k++) {
            float4 t = cmp4[base + (long)k * strideK];
            s.x += t.x; s.y += t.y; s.z += t.z; s.w += t.w;
        }
        *(float4*)&Sx[r * SX_STRIDE + D_ + c4 * 4] = s;
    }
    // (first __syncthreads inside layer<> orders these stores before any read)

    // L0: [sig|csum] (256) -> h0 (132), folded weight
    layer<2 * D_, H_, 5, 128, true >(Sx, SX_STRIDE, Sh, SH_STRIDE, g_Wcat, g_b0c, Sw, tid);
    // L1: 132 -> 132  (reuse Sx region as activation buffer, stride 132)
    layer<H_, H_, 5, H_, true >(Sh, SH_STRIDE, Sx, SH_STRIDE, W1, b1, Sw, tid);
    // L2: 132 -> 132
    layer<H_, H_, 5, H_, true >(Sx, SH_STRIDE, Sh, SH_STRIDE, W2, b2, Sw, tid);
    // L3: 132 -> 128, write straight to global (no relu)
    layer<H_, D_, 4, H_, false>(Sh, SH_STRIDE, out + row0 * D_, D_, W3, b3, Sw, tid);
}

extern "C" void kernel_launch(void* const* d_in, const int* in_sizes, int n_in,
                              void* d_out, int out_size)
{
    const float* sig   = (const float*)d_in[0];
    const float* comps = (const float*)d_in[1];
    const float* Wm    = (const float*)d_in[2];
    const float* bm    = (const float*)d_in[3];
    const float* Wu    = (const float*)d_in[4];
    const float* bu    = (const float*)d_in[5];
    const float* W0    = (const float*)d_in[6];
    const float* b0    = (const float*)d_in[7];
    const float* W1    = (const float*)d_in[8];
    const float* b1    = (const float*)d_in[9];
    const float* W2    = (const float*)d_in[10];
    const float* b2    = (const float*)d_in[11];
    const float* W3    = (const float*)d_in[12];
    const float* b3    = (const float*)d_in[13];
    float* out = (float*)d_out;

    const int B = in_sizes[0] / D_;           // 65536
    const int K = in_sizes[1] / in_sizes[0];  // 8

    cudaFuncSetAttribute(fused_kernel,
                         cudaFuncAttributeMaxDynamicSharedMemorySize, SMEM_BYTES);

    precompA<<<D_, D_>>>(Wm, bm, Wu, bu, K);
    precompB<<<H_, D_>>>(W0, b0);
    fused_kernel<<<B / ROWS, TPB, SMEM_BYTES>>>(sig, comps,
                                                W1, b1, W2, b2, W3, b3,
                                                out, B, K);
}

// round 3
// speedup vs baseline: 1.9984x; 1.9984x over previous
#include <cuda_runtime.h>
#include <cuda_bf16.h>
#include <cstdint>

#define D_  128
#define H_  132
#define M_  128      // batch rows per CTA
#define TPB 256

// ---------------------------------------------------------------------------
// Device-global precomputed buffers
// ---------------------------------------------------------------------------
__device__ float g_Wc[D_ * D_];          // Wu @ Wm
__device__ float g_bc[D_];               // K*(Wu@bm) + bu
__device__ float g_Wcat[H_ * 2 * D_];    // folded layer-0 weight [132][256]
__device__ float g_b0c[H_];
// weight chunks: 13 chunks, each [hi/lo][144 n][72 k] bf16 (41472 B contiguous)
__device__ __align__(16) __nv_bfloat16 g_Bw[13][2][144 * 72];
__device__ float g_biasf[4][144];

// ---------------------------------------------------------------------------
// SMEM map (bytes)
//   A_hi [128][264] bf16 (row stride 528B)   :      0 .. 67584
//   A_lo                                      :  67584 .. 135168
//   B buf0 (hi 20736 | lo 20736)              : 135168 .. 176640
//   B buf1                                    : 176640 .. 218112
//   bias [4][144] f32                         : 218112 .. 220416
// ---------------------------------------------------------------------------
#define A_HI    0
#define A_LO    67584
#define ASTRIDE 528
#define B_OFF   135168
#define B_BUF   41472
#define B_HALF  20736
#define BSTRIDE 144
#define BIAS_OFF 218112
#define SMEM_BYTES 220416

// ---------------------------------------------------------------------------
// PTX helpers (all plain sm_80+ features)
// ---------------------------------------------------------------------------
__device__ __forceinline__ uint32_t smem_u32(const void* p) {
    uint32_t a;
    asm("{ .reg .u64 t; cvta.to.shared.u64 t, %1; cvt.u32.u64 %0, t; }" : "=r"(a) : "l"(p));
    return a;
}
#define LDSM4(r, a) \
    asm volatile("ldmatrix.sync.aligned.m8n8.x4.shared.b16 {%0,%1,%2,%3}, [%4];" \
                 : "=r"((r)[0]), "=r"((r)[1]), "=r"((r)[2]), "=r"((r)[3]) : "r"(a))
#define LDSM2(r, a) \
    asm volatile("ldmatrix.sync.aligned.m8n8.x2.shared.b16 {%0,%1}, [%2];" \
                 : "=r"((r)[0]), "=r"((r)[1]) : "r"(a))
#define MMA(c, A, Bv) \
    asm volatile("mma.sync.aligned.m16n8k16.row.col.f32.bf16.bf16.f32 " \
                 "{%0,%1,%2,%3}, {%4,%5,%6,%7}, {%8,%9}, {%0,%1,%2,%3};" \
                 : "+f"((c)[0]), "+f"((c)[1]), "+f"((c)[2]), "+f"((c)[3]) \
                 : "r"((A)[0]), "r"((A)[1]), "r"((A)[2]), "r"((A)[3]), \
                   "r"((Bv)[0]), "r"((Bv)[1]))
#define CP_WAIT0()  asm volatile("cp.async.wait_group 0;" ::: "memory")
#define CP_COMMIT() asm volatile("cp.async.commit_group;" ::: "memory")

__device__ __forceinline__ uint32_t pack2(__nv_bfloat16 a, __nv_bfloat16 b) {
    uint16_t x = *(uint16_t*)&a, y = *(uint16_t*)&b;
    return (uint32_t)x | ((uint32_t)y << 16);
}
__device__ __forceinline__ void split_bf16(float x, __nv_bfloat16& h, __nv_bfloat16& l) {
    h = __float2bfloat16_rn(x);
    l = __float2bfloat16_rn(x - __bfloat162float(h));
}

// stage weight chunk cid into B buf (cid&1) via cp.async (2592 x 16B)
__device__ __forceinline__ void stage_chunk(uint32_t sb, int cid, int tid) {
    const char* g = (const char*)&g_Bw[cid][0][0];
    uint32_t s = sb + B_OFF + (uint32_t)(cid & 1) * B_BUF;
#pragma unroll
    for (int j = 0; j < 11; j++) {
        int idx = tid + j * TPB;
        if (idx < 2592)
            asm volatile("cp.async.cg.shared.global [%0], [%1], 16;"
                         :: "r"(s + idx * 16), "l"(g + idx * 16));
    }
    CP_COMMIT();
}

// ---------------------------------------------------------------------------
// Precompute kernels
// ---------------------------------------------------------------------------
__global__ void precompA(const float* __restrict__ Wm, const float* __restrict__ bm,
                         const float* __restrict__ Wu, const float* __restrict__ bu, int K)
{
    __shared__ float sWu[D_];
    int f = blockIdx.x, d = threadIdx.x;
    sWu[d] = Wu[f * D_ + d];
    __syncthreads();
    float acc = 0.f;
#pragma unroll 8
    for (int e = 0; e < D_; e++) acc += sWu[e] * Wm[e * D_ + d];
    g_Wc[f * D_ + d] = acc;
    if (d == 0) {
        float s = 0.f;
        for (int e = 0; e < D_; e++) s += sWu[e] * bm[e];
        g_bc[f] = (float)K * s + bu[f];
    }
}

__global__ void precompB(const float* __restrict__ W0, const float* __restrict__ b0)
{
    __shared__ float sW0r[D_];
    int o = blockIdx.x, d = threadIdx.x;
    sW0r[d] = W0[o * 2 * D_ + D_ + d];
    g_Wcat[o * 2 * D_ + d] = W0[o * 2 * D_ + d];
    __syncthreads();
    float acc = 0.f;
#pragma unroll 8
    for (int f = 0; f < D_; f++) acc += sW0r[f] * g_Wc[f * D_ + d];
    g_Wcat[o * 2 * D_ + D_ + d] = acc;
    if (d == 0) {
        float s = 0.f;
        for (int f = 0; f < D_; f++) s += sW0r[f] * g_bc[f];
        g_b0c[o] = s + b0[o];
    }
}

// Build split-bf16 weight chunks + bias table.  Chunk cid -> (layer, c):
//   cid 0-3: L0 (K-chunks of 64);  4-6: L1;  7-9: L2;  10-12: L3 (chunks of 48)
__global__ void precompBW(const float* __restrict__ W1, const float* __restrict__ b1,
                          const float* __restrict__ W2, const float* __restrict__ b2,
                          const float* __restrict__ W3, const float* __restrict__ b3)
{
    int cid = blockIdx.x;
    int l, c;
    if (cid < 4) { l = 0; c = cid; } else { l = 1 + (cid - 4) / 3; c = (cid - 4) % 3; }
    const int ck   = (l == 0) ? 64 : 48;
    const int Kl   = (l == 0) ? 256 : H_;     // valid K extent
    const int Nl   = (l == 3) ? D_ : H_;
    if (c == 0) {
        for (int t = threadIdx.x; t < 144; t += blockDim.x) {
            float bv = 0.f;
            if (l == 0)      { if (t < H_) bv = g_b0c[t]; }
            else if (l == 1) { if (t < H_) bv = b1[t]; }
            else if (l == 2) { if (t < H_) bv = b2[t]; }
            else             { if (t < D_) bv = b3[t]; }
            g_biasf[l][t] = bv;
        }
    }
    for (int idx = threadIdx.x; idx < 144 * 72; idx += blockDim.x) {
        int n = idx / 72, kk = idx % 72;
        int k = c * ck + kk;
        float w = 0.f;
        if (kk < ck && n < Nl && k < Kl) {
            if (l == 0)      w = g_Wcat[n * 256 + k];
            else if (l == 1) w = W1[n * H_ + k];
            else if (l == 2) w = W2[n * H_ + k];
            else             w = W3[n * H_ + k];
        }
        __nv_bfloat16 h, lo;
        split_bf16(w, h, lo);
        g_Bw[cid][0][idx] = h;
        g_Bw[cid][1][idx] = lo;
    }
}

// ---------------------------------------------------------------------------
// One layer: NC weight chunks x KSTEPS k-steps, NT n8-tiles, then epilogue.
// A reads and next-A writes are warp-private (each warp owns rows R0..R0+15).
// ---------------------------------------------------------------------------
template<int NT, int KSTEPS, int NC, bool RELU, bool LAST>
__device__ __forceinline__ void run_layer(char* smem, uint32_t sb, int layer, int& cid,
                                          int tid, int wid, int lane,
                                          float* __restrict__ gout)
{
    float acc[NT][4];
#pragma unroll
    for (int t = 0; t < NT; t++)
#pragma unroll
        for (int j = 0; j < 4; j++) acc[t][j] = 0.f;

    const int R0 = wid * 16;
    const int ln = lane & 15;
    const int kchunk = (KSTEPS == 4) ? 64 : 48;
    // per-lane invariant ldmatrix addresses
    const uint32_t aAh0 = sb + A_HI + (uint32_t)(R0 + ln) * ASTRIDE + (uint32_t)(lane >> 4) * 16;
    const uint32_t bB0  = sb + B_OFF + (uint32_t)(ln & 7) * BSTRIDE + (uint32_t)(ln >> 3) * 16;

    for (int c = 0; c < NC; c++) {
        CP_WAIT0();            // chunk cid staged
        __syncthreads();       // all warps done with the other B buf
        if (cid + 1 < 13) stage_chunk(sb, cid + 1, tid);   // overlap with MMA

        const uint32_t bbuf = bB0 + (uint32_t)(cid & 1) * B_BUF;
        const uint32_t ak   = aAh0 + (uint32_t)(c * kchunk) * 2;
#pragma unroll
        for (int s = 0; s < KSTEPS; s++) {
            uint32_t Ah[4], Al[4];
            LDSM4(Ah, ak + s * 32);
            LDSM4(Al, ak + s * 32 + (A_LO - A_HI));
#pragma unroll
            for (int t = 0; t < NT; t++) {
                uint32_t Bh[2], Bl[2];
                uint32_t ba = bbuf + (uint32_t)t * (8 * BSTRIDE) + s * 32;
                LDSM2(Bh, ba);
                LDSM2(Bl, ba + B_HALF);
                MMA(acc[t], Ah, Bh);
                MMA(acc[t], Al, Bh);
                MMA(acc[t], Ah, Bl);
            }
        }
        cid++;
    }

    // ---- epilogue (warp-private rows)
    const float* bias = (const float*)(smem + BIAS_OFF) + layer * 144;
    const int r0 = R0 + (lane >> 2);
#pragma unroll
    for (int t = 0; t < NT; t++) {
        const int col = t * 8 + (lane & 3) * 2;
        const float b0 = bias[col], b1 = bias[col + 1];
        float v00 = acc[t][0] + b0, v01 = acc[t][1] + b1;
        float v10 = acc[t][2] + b0, v11 = acc[t][3] + b1;
        if (RELU) {
            v00 = fmaxf(v00, 0.f); v01 = fmaxf(v01, 0.f);
            v10 = fmaxf(v10, 0.f); v11 = fmaxf(v11, 0.f);
        }
        if (LAST) {
            *(float2*)(gout + (long)r0 * D_ + col)       = make_float2(v00, v01);
            *(float2*)(gout + (long)(r0 + 8) * D_ + col) = make_float2(v10, v11);
        } else {
            __nv_bfloat16 h0, l0, h1, l1;
            split_bf16(v00, h0, l0); split_bf16(v01, h1, l1);
            *(uint32_t*)(smem + A_HI + r0 * ASTRIDE + col * 2) = pack2(h0, h1);
            *(uint32_t*)(smem + A_LO + r0 * ASTRIDE + col * 2) = pack2(l0, l1);
            split_bf16(v10, h0, l0); split_bf16(v11, h1, l1);
            *(uint32_t*)(smem + A_HI + (r0 + 8) * ASTRIDE + col * 2) = pack2(h0, h1);
            *(uint32_t*)(smem + A_LO + (r0 + 8) * ASTRIDE + col * 2) = pack2(l0, l1);
        }
    }
    __syncwarp();   // next layer's ldmatrix reads lanes' cross-written rows
}

__global__ __launch_bounds__(TPB, 1)
void fused_mma(const float* __restrict__ sig, const float* __restrict__ comps,
               float* __restrict__ out, int B, int K)
{
    extern __shared__ __align__(16) char smem[];
    const uint32_t sb = smem_u32(smem);
    const int tid = threadIdx.x, wid = tid >> 5, lane = tid & 31;
    const long rbase = (long)blockIdx.x * M_;

    stage_chunk(sb, 0, tid);     // prefetch first weight chunk early

    // bias table
    for (int j = tid; j < 576; j += TPB)
        ((float*)(smem + BIAS_OFF))[j] = ((const float*)g_biasf)[j];

    // ---- layer-0 A tile: cols 0-127 signal, 128-255 csum; split hi/lo bf16
    {
        const float4* sig4 = (const float4*)sig;
        const float4* cmp4 = (const float4*)comps;
        const long sK = (long)B * 32;
        for (int idx = tid; idx < 4096; idx += TPB) {
            int half = idx >> 11, t = idx & 2047;
            int r = t >> 4, g = t & 15;
            long ga = (rbase + r) * 32 + g * 2;
            float4 v0, v1;
            if (half == 0) { v0 = sig4[ga]; v1 = sig4[ga + 1]; }
            else {
                v0 = make_float4(0.f, 0.f, 0.f, 0.f); v1 = v0;
#pragma unroll 8
                for (int k = 0; k < 8; k++) {
                    float4 a = cmp4[ga + (long)k * sK];
                    float4 b = cmp4[ga + 1 + (long)k * sK];
                    v0.x += a.x; v0.y += a.y; v0.z += a.z; v0.w += a.w;
                    v1.x += b.x; v1.y += b.y; v1.z += b.z; v1.w += b.w;
                }
            }
            float f[8] = {v0.x, v0.y, v0.z, v0.w, v1.x, v1.y, v1.z, v1.w};
            uint32_t hh[4], ll[4];
#pragma unroll
            for (int j = 0; j < 4; j++) {
                __nv_bfloat16 h0, l0, h1, l1;
                split_bf16(f[2 * j], h0, l0);
                split_bf16(f[2 * j + 1], h1, l1);
                hh[j] = pack2(h0, h1);
                ll[j] = pack2(l0, l1);
            }
            int cols = half * 128 + g * 8;
            *(uint4*)(smem + A_HI + r * ASTRIDE + cols * 2) = make_uint4(hh[0], hh[1], hh[2], hh[3]);
            *(uint4*)(smem + A_LO + r * ASTRIDE + cols * 2) = make_uint4(ll[0], ll[1], ll[2], ll[3]);
        }
    }
    // (first CP_WAIT0 + __syncthreads inside run_layer orders A/bias stores)

    int cid = 0;
    float* gout = out + rbase * D_;
    run_layer<18, 4, 4, true,  false>(smem, sb, 0, cid, tid, wid, lane, nullptr);
    run_layer<18, 3, 3, true,  false>(smem, sb, 1, cid, tid, wid, lane, nullptr);
    run_layer<18, 3, 3, true,  false>(smem, sb, 2, cid, tid, wid, lane, nullptr);
    run_layer<16, 3, 3, false, true >(smem, sb, 3, cid, tid, wid, lane, gout);
}

// ---------------------------------------------------------------------------
extern "C" void kernel_launch(void* const* d_in, const int* in_sizes, int n_in,
                              void* d_out, int out_size)
{
    const float* sig   = (const float*)d_in[0];
    const float* comps = (const float*)d_in[1];
    const float* Wm    = (const float*)d_in[2];
    const float* bm    = (const float*)d_in[3];
    const float* Wu    = (const float*)d_in[4];
    const float* bu    = (const float*)d_in[5];
    const float* W0    = (const float*)d_in[6];
    const float* b0    = (const float*)d_in[7];
    const float* W1    = (const float*)d_in[8];
    const float* b1    = (const float*)d_in[9];
    const float* W2    = (const float*)d_in[10];
    const float* b2    = (const float*)d_in[11];
    const float* W3    = (const float*)d_in[12];
    const float* b3    = (const float*)d_in[13];
    float* out = (float*)d_out;

    const int B = in_sizes[0] / D_;           // 65536
    const int K = in_sizes[1] / in_sizes[0];  // 8

    cudaFuncSetAttribute(fused_mma,
                         cudaFuncAttributeMaxDynamicSharedMemorySize, SMEM_BYTES);

    precompA<<<D_, D_>>>(Wm, bm, Wu, bu, K);
    precompB<<<H_, D_>>>(W0, b0);
    precompBW<<<13, 256>>>(W1, b1, W2, b2, W3, b3);
    fused_mma<<<B / M_, TPB, SMEM_BYTES>>>(sig, comps, out, B, K);
}

// round 5
// speedup vs baseline: 2.3714x; 1.1867x over previous
#include <cuda_runtime.h>
#include <cuda_bf16.h>
#include <cstdint>

#define D_  128
#define H_  132
#define M_  64       // batch rows per CTA
#define TPB 128

// ---------------------------------------------------------------------------
// Device-global precomputed buffers
// ---------------------------------------------------------------------------
__device__ float g_Wc[D_ * D_];          // Wu @ Wm
__device__ float g_bc[D_];               // K*(Wu@bm) + bu
__device__ float g_Wcat[H_ * 2 * D_];    // folded layer-0 weight [132][256]
__device__ float g_b0c[H_];
// 23 weight chunks (L0:8, L1:5, L2:5, L3:5), each [hi/lo][144 n][40 k] bf16
// (k rows padded to 40 entries = 80 B so SMEM rows stay 16B-aligned)
__device__ __align__(16) __nv_bfloat16 g_Bw[23][2][144 * 40];
__device__ float g_biasf[4][144];

// ---------------------------------------------------------------------------
// SMEM map (bytes)
//   A_hi [64][264] bf16 (row stride 528B)  :      0 .. 33792
//   A_lo                                    :  33792 .. 67584
//   B buf0 (hi 11520 | lo 11520)            :  67584 .. 90624
//   B buf1                                  :  90624 .. 113664
// ---------------------------------------------------------------------------
#define A_HI     0
#define A_LO     33792
#define ASTRIDE  528
#define B_OFF    67584
#define B_BUF    23040
#define B_HALF   11520
#define BSTRIDE  80
#define SMEM_BYTES 113664
#define NCHUNK   23

// ---------------------------------------------------------------------------
// PTX helpers (plain sm_80+ features only)
// ---------------------------------------------------------------------------
__device__ __forceinline__ uint32_t smem_u32(const void* p) {
    uint32_t a;
    asm("{ .reg .u64 t; cvta.to.shared.u64 t, %1; cvt.u32.u64 %0, t; }" : "=r"(a) : "l"(p));
    return a;
}
#define LDSM4(r, a) \
    asm volatile("ldmatrix.sync.aligned.m8n8.x4.shared.b16 {%0,%1,%2,%3}, [%4];" \
                 : "=r"((r)[0]), "=r"((r)[1]), "=r"((r)[2]), "=r"((r)[3]) : "r"(a))
#define LDSM2(r, a) \
    asm volatile("ldmatrix.sync.aligned.m8n8.x2.shared.b16 {%0,%1}, [%2];" \
                 : "=r"((r)[0]), "=r"((r)[1]) : "r"(a))
#define MMA(c, A, Bv) \
    asm volatile("mma.sync.aligned.m16n8k16.row.col.f32.bf16.bf16.f32 " \
                 "{%0,%1,%2,%3}, {%4,%5,%6,%7}, {%8,%9}, {%0,%1,%2,%3};" \
                 : "+f"((c)[0]), "+f"((c)[1]), "+f"((c)[2]), "+f"((c)[3]) \
                 : "r"((A)[0]), "r"((A)[1]), "r"((A)[2]), "r"((A)[3]), \
                   "r"((Bv)[0]), "r"((Bv)[1]))
#define CP_WAIT0()  asm volatile("cp.async.wait_group 0;" ::: "memory")
#define CP_COMMIT() asm volatile("cp.async.commit_group;" ::: "memory")

__device__ __forceinline__ uint32_t pack2(__nv_bfloat16 a, __nv_bfloat16 b) {
    uint16_t x = *(uint16_t*)&a, y = *(uint16_t*)&b;
    return (uint32_t)x | ((uint32_t)y << 16);
}
__device__ __forceinline__ void split_bf16(float x, __nv_bfloat16& h, __nv_bfloat16& l) {
    h = __float2bfloat16_rn(x);
    l = __float2bfloat16_rn(x - __bfloat162float(h));
}

// stage weight chunk cid into B buf (cid&1) via cp.async (1440 x 16B)
__device__ __forceinline__ void stage_chunk(uint32_t sb, int cid, int tid) {
    const char* g = (const char*)&g_Bw[cid][0][0];
    uint32_t s = sb + B_OFF + (uint32_t)(cid & 1) * B_BUF;
#pragma unroll
    for (int j = 0; j < 12; j++) {
        int idx = tid + j * TPB;
        if (idx < 1440)
            asm volatile("cp.async.cg.shared.global [%0], [%1], 16;"
                         :: "r"(s + idx * 16), "l"(g + idx * 16));
    }
    CP_COMMIT();
}

// ---------------------------------------------------------------------------
// Precompute kernels
// ---------------------------------------------------------------------------
__global__ void precompA(const float* __restrict__ Wm, const float* __restrict__ bm,
                         const float* __restrict__ Wu, const float* __restrict__ bu, int K)
{
    __shared__ float sWu[D_];
    int f = blockIdx.x, d = threadIdx.x;
    sWu[d] = Wu[f * D_ + d];
    __syncthreads();
    float acc = 0.f;
#pragma unroll 8
    for (int e = 0; e < D_; e++) acc += sWu[e] * Wm[e * D_ + d];
    g_Wc[f * D_ + d] = acc;
    if (d == 0) {
        float s = 0.f;
        for (int e = 0; e < D_; e++) s += sWu[e] * bm[e];
        g_bc[f] = (float)K * s + bu[f];
    }
}

__global__ void precompB(const float* __restrict__ W0, const float* __restrict__ b0)
{
    __shared__ float sW0r[D_];
    int o = blockIdx.x, d = threadIdx.x;
    sW0r[d] = W0[o * 2 * D_ + D_ + d];
    g_Wcat[o * 2 * D_ + d] = W0[o * 2 * D_ + d];
    __syncthreads();
    float acc = 0.f;
#pragma unroll 8
    for (int f = 0; f < D_; f++) acc += sW0r[f] * g_Wc[f * D_ + d];
    g_Wcat[o * 2 * D_ + D_ + d] = acc;
    if (d == 0) {
        float s = 0.f;
        for (int f = 0; f < D_; f++) s += sW0r[f] * g_bc[f];
        g_b0c[o] = s + b0[o];
    }
}

// Split-bf16 weight chunks (k-chunks of 32, rows padded to 40) + bias table.
// cid 0-7: L0 ; 8-12: L1 ; 13-17: L2 ; 18-22: L3
__global__ void precompBW(const float* __restrict__ W1, const float* __restrict__ b1,
                          const float* __restrict__ W2, const float* __restrict__ b2,
                          const float* __restrict__ W3, const float* __restrict__ b3)
{
    int cid = blockIdx.x;
    int l, c;
    if (cid < 8) { l = 0; c = cid; } else { l = 1 + (cid - 8) / 5; c = (cid - 8) % 5; }
    const int Kl = (l == 0) ? 256 : H_;
    const int Nl = (l == 3) ? D_ : H_;
    if (c == 0) {
        for (int t = threadIdx.x; t < 144; t += blockDim.x) {
            float bv = 0.f;
            if (l == 0)      { if (t < H_) bv = g_b0c[t]; }
            else if (l == 1) { if (t < H_) bv = b1[t]; }
            else if (l == 2) { if (t < H_) bv = b2[t]; }
            else             { if (t < D_) bv = b3[t]; }
            g_biasf[l][t] = bv;
        }
    }
    for (int idx = threadIdx.x; idx < 144 * 40; idx += blockDim.x) {
        int n = idx / 40, kk = idx % 40;
        int k = c * 32 + kk;
        float w = 0.f;
        if (kk < 32 && n < Nl && k < Kl) {
            if (l == 0)      w = g_Wcat[n * 256 + k];
            else if (l == 1) w = W1[n * H_ + k];
            else if (l == 2) w = W2[n * H_ + k];
            else             w = W3[n * H_ + k];
        }
        __nv_bfloat16 h, lo;
        split_bf16(w, h, lo);
        g_Bw[cid][0][idx] = h;
        g_Bw[cid][1][idx] = lo;
    }
}

// ---------------------------------------------------------------------------
// One layer: NC k32-chunks (2 k16-steps each), NT n8-tiles, then epilogue.
// Each warp owns a 16-row slab; A reads and next-A writes are warp-private.
// ZPAD: L0 epilogue zeroes A cols 144..159 (K padding for layers 1-3).
// ---------------------------------------------------------------------------
template<int NT, int NC, bool RELU, bool LAST, bool ZPAD>
__device__ __forceinline__ void run_layer(char* smem, uint32_t sb, int layer, int& cid,
                                          int tid, int wid, int lane,
                                          float* __restrict__ gout)
{
    float acc[NT][4];
#pragma unroll
    for (int t = 0; t < NT; t++)
#pragma unroll
        for (int j = 0; j < 4; j++) acc[t][j] = 0.f;

    const int R0 = wid * 16;
    const int ln = lane & 15;
    const uint32_t aAh0 = sb + A_HI + (uint32_t)(R0 + ln) * ASTRIDE + (uint32_t)(lane >> 4) * 16;
    const uint32_t bB0  = sb + B_OFF + (uint32_t)(ln & 7) * BSTRIDE + (uint32_t)(ln >> 3) * 16;

    for (int c = 0; c < NC; c++) {
        CP_WAIT0();            // chunk cid staged
        __syncthreads();       // all warps done with the other B buf
        if (cid + 1 < NCHUNK) stage_chunk(sb, cid + 1, tid);   // overlap with MMA

        const uint32_t bbuf = bB0 + (uint32_t)(cid & 1) * B_BUF;
        const uint32_t ak   = aAh0 + (uint32_t)c * 64;
#pragma unroll
        for (int s = 0; s < 2; s++) {
            uint32_t Ah[4], Al[4];
            LDSM4(Ah, ak + s * 32);
            LDSM4(Al, ak + s * 32 + (A_LO - A_HI));
#pragma unroll
            for (int t = 0; t < NT; t++) {
                uint32_t Bh[2], Bl[2];
                uint32_t ba = bbuf + (uint32_t)t * (8 * BSTRIDE) + s * 32;
                LDSM2(Bh, ba);
                LDSM2(Bl, ba + B_HALF);
                MMA(acc[t], Ah, Bh);
                MMA(acc[t], Al, Bh);
                MMA(acc[t], Ah, Bl);
            }
        }
        cid++;
    }

    // ---- epilogue (warp-private rows); bias via LDG (L2-resident)
    const float* bias = &g_biasf[layer][0];
    const int r0 = R0 + (lane >> 2);
#pragma unroll
    for (int t = 0; t < NT; t++) {
        const int col = t * 8 + (lane & 3) * 2;
        const float b0 = __ldg(bias + col), b1 = __ldg(bias + col + 1);
        float v00 = acc[t][0] + b0, v01 = acc[t][1] + b1;
        float v10 = acc[t][2] + b0, v11 = acc[t][3] + b1;
        if (RELU) {
            v00 = fmaxf(v00, 0.f); v01 = fmaxf(v01, 0.f);
            v10 = fmaxf(v10, 0.f); v11 = fmaxf(v11, 0.f);
        }
        if (LAST) {
            *(float2*)(gout + (long)r0 * D_ + col)       = make_float2(v00, v01);
            *(float2*)(gout + (long)(r0 + 8) * D_ + col) = make_float2(v10, v11);
        } else {
            __nv_bfloat16 h0, l0, h1, l1;
            split_bf16(v00, h0, l0); split_bf16(v01, h1, l1);
            *(uint32_t*)(smem + A_HI + r0 * ASTRIDE + col * 2) = pack2(h0, h1);
            *(uint32_t*)(smem + A_LO + r0 * ASTRIDE + col * 2) = pack2(l0, l1);
            split_bf16(v10, h0, l0); split_bf16(v11, h1, l1);
            *(uint32_t*)(smem + A_HI + (r0 + 8) * ASTRIDE + col * 2) = pack2(h0, h1);
            *(uint32_t*)(smem + A_LO + (r0 + 8) * ASTRIDE + col * 2) = pack2(l0, l1);
        }
    }
    if (ZPAD) {
        // zero A cols 144..159 of this warp's 16 rows (hi & lo)
        const int zr = R0 + (lane >> 1);
        const int zc = 144 + (lane & 1) * 8;
        uint4 z = make_uint4(0u, 0u, 0u, 0u);
        *(uint4*)(smem + A_HI + zr * ASTRIDE + zc * 2) = z;
        *(uint4*)(smem + A_LO + zr * ASTRIDE + zc * 2) = z;
    }
    __syncwarp();   // next layer's ldmatrix reads lanes' cross-written rows
}

__global__ __launch_bounds__(TPB, 2)
void fused_mma(const float* __restrict__ sig, const float* __restrict__ comps,
               float* __restrict__ out, int B, int K)
{
    extern __shared__ __align__(16) char smem[];
    const uint32_t sb = smem_u32(smem);
    const int tid = threadIdx.x, wid = tid >> 5, lane = tid & 31;
    const long rbase = (long)blockIdx.x * M_;

    stage_chunk(sb, 0, tid);     // prefetch first weight chunk early

    // ---- layer-0 A tile: cols 0-127 signal, 128-255 csum; split hi/lo bf16
    {
        const float4* sig4 = (const float4*)sig;
        const float4* cmp4 = (const float4*)comps;
        const long sK = (long)B * 32;
        for (int idx = tid; idx < 2048; idx += TPB) {
            int half = idx >> 10, t = idx & 1023;
            int r = t >> 4, g = t & 15;
            long ga = (rbase + r) * 32 + g * 2;
            float4 v0, v1;
            if (half == 0) { v0 = sig4[ga]; v1 = sig4[ga + 1]; }
            else {
                v0 = make_float4(0.f, 0.f, 0.f, 0.f); v1 = v0;
#pragma unroll 8
                for (int k = 0; k < 8; k++) {
                    float4 a = cmp4[ga + (long)k * sK];
                    float4 b = cmp4[ga + 1 + (long)k * sK];
                    v0.x += a.x; v0.y += a.y; v0.z += a.z; v0.w += a.w;
                    v1.x += b.x; v1.y += b.y; v1.z += b.z; v1.w += b.w;
                }
            }
            float f[8] = {v0.x, v0.y, v0.z, v0.w, v1.x, v1.y, v1.z, v1.w};
            uint32_t hh[4], ll[4];
#pragma unroll
            for (int j = 0; j < 4; j++) {
                __nv_bfloat16 h0, l0, h1, l1;
                split_bf16(f[2 * j], h0, l0);
                split_bf16(f[2 * j + 1], h1, l1);
                hh[j] = pack2(h0, h1);
                ll[j] = pack2(l0, l1);
            }
            int cols = half * 128 + g * 8;
            *(uint4*)(smem + A_HI + r * ASTRIDE + cols * 2) = make_uint4(hh[0], hh[1], hh[2], hh[3]);
            *(uint4*)(smem + A_LO + r * ASTRIDE + cols * 2) = make_uint4(ll[0], ll[1], ll[2], ll[3]);
        }
    }
    // (first CP_WAIT0 + __syncthreads inside run_layer orders A stores)

    int cid = 0;
    float* gout = out + rbase * D_;
    run_layer<18, 8, true,  false, true >(smem, sb, 0, cid, tid, wid, lane, nullptr);
    run_layer<18, 5, true,  false, false>(smem, sb, 1, cid, tid, wid, lane, nullptr);
    run_layer<18, 5, true,  false, false>(smem, sb, 2, cid, tid, wid, lane, nullptr);
    run_layer<16, 5, false, true,  false>(smem, sb, 3, cid, tid, wid, lane, gout);
}

// ---------------------------------------------------------------------------
extern "C" void kernel_launch(void* const* d_in, const int* in_sizes, int n_in,
                              void* d_out, int out_size)
{
    const float* sig   = (const float*)d_in[0];
    const float* comps = (const float*)d_in[1];
    const float* Wm    = (const float*)d_in[2];
    const float* bm    = (const float*)d_in[3];
    const float* Wu    = (const float*)d_in[4];
    const float* bu    = (const float*)d_in[5];
    const float* W0    = (const float*)d_in[6];
    const float* b0    = (const float*)d_in[7];
    const float* W1    = (const float*)d_in[8];
    const float* b1    = (const float*)d_in[9];
    const float* W2    = (const float*)d_in[10];
    const float* b2    = (const float*)d_in[11];
    const float* W3    = (const float*)d_in[12];
    const float* b3    = (const float*)d_in[13];
    float* out = (float*)d_out;

    const int B = in_sizes[0] / D_;           // 65536
    const int K = in_sizes[1] / in_sizes[0];  // 8

    cudaFuncSetAttribute(fused_mma,
                         cudaFuncAttributeMaxDynamicSharedMemorySize, SMEM_BYTES);

    precompA<<<D_, D_>>>(Wm, bm, Wu, bu, K);
    precompB<<<H_, D_>>>(W0, b0);
    precompBW<<<NCHUNK, 256>>>(W1, b1, W2, b2, W3, b3);
    fused_mma<<<B / M_, TPB, SMEM_BYTES>>>(sig, comps, out, B, K);
}